// round 6
// baseline (speedup 1.0000x reference)
#include <cuda_runtime.h>
#include <cstdint>

// Problem constants
#define B_    4
#define L_    1024
#define V_    1280
#define E_    768
#define NBIN  8
#define NHID  32

// Output layout: concat(logits[B,L,8,V], tte[B,L,V], mask[B,L,8,V]) fp32
#define TTE_OFF    ((size_t)B_ * L_ * NBIN * V_)                 // 41943040
#define MASK_OFF   (TTE_OFF + (size_t)B_ * L_ * V_)              // 47185920

// Scratch: x = h @ W1, stored TRANSPOSED per row: g_x[row*256 + h*8 + n]
__device__ float g_x[(size_t)B_ * L_ * NBIN * NHID];
// Seed table: g_seed[b][chunk][v] = next occurrence index >= (chunk+1)*32
__device__ int g_seed[(size_t)B_ * 32 * V_];

typedef unsigned long long u64;
union F4U2 { float4 f; u64 u[2]; };

__device__ __forceinline__ u64 pk(float lo, float hi) {
    u64 r; asm("mov.b64 %0, {%1,%2};" : "=l"(r) : "f"(lo), "f"(hi)); return r;
}
__device__ __forceinline__ void upk(u64 v, float& lo, float& hi) {
    asm("mov.b64 {%0,%1}, %2;" : "=f"(lo), "=f"(hi) : "l"(v));
}
__device__ __forceinline__ void fma2(u64& d, u64 a, u64 b) {
    asm("fma.rn.f32x2 %0, %1, %2, %0;" : "+l"(d) : "l"(a), "l"(b));
}

// ---------------------------------------------------------------------------
// Kernel 1: x = h @ W1   (M=4096, K=768, N=256).  128x64 tile, 256 threads,
// 8x4 per thread, diagonal-packed FFMA2.  Writes g_x in [h][bin] layout.
// ---------------------------------------------------------------------------
__global__ __launch_bounds__(256) void k_gemm1(const float* __restrict__ A,
                                               const float* __restrict__ W1) {
    __shared__ float As[16][132];   // [k][row]
    __shared__ float Bs[16][68];    // [k][col]
    const int K = E_, N = NBIN * NHID;
    int bx = blockIdx.x;                 // 0..3   (N/64)
    int by = blockIdx.y;                 // 0..31  (M/128)
    int tid = threadIdx.x;
    int tx = tid & 15, ty = tid >> 4;
    int rowBase = by * 128, colBase = bx * 64;

    u64 c[4][4];
#pragma unroll
    for (int i = 0; i < 4; i++)
#pragma unroll
        for (int j = 0; j < 4; j++) c[i][j] = 0;

    for (int k0 = 0; k0 < K; k0 += 16) {
#pragma unroll
        for (int p = 0; p < 8; p++) {          // 128x16 A tile
            int idx = tid + p * 256;
            int r = idx >> 4, cc = idx & 15;
            As[cc][r] = A[(size_t)(rowBase + r) * K + k0 + cc];
        }
#pragma unroll
        for (int p = 0; p < 4; p++) {          // 16x64 B tile
            int idx = tid + p * 256;
            int r = idx >> 6, cc = idx & 63;
            Bs[r][cc] = W1[(size_t)(k0 + r) * N + colBase + cc];
        }
        __syncthreads();
#pragma unroll
        for (int kk = 0; kk < 16; kk++) {
            F4U2 alo, ahi, bv;
            alo.f = *(const float4*)&As[kk][ty * 8];
            ahi.f = *(const float4*)&As[kk][ty * 8 + 4];
            bv.f  = *(const float4*)&Bs[kk][tx * 4];
            u64 ap0 = alo.u[0], ap1 = alo.u[1], ap2 = ahi.u[0], ap3 = ahi.u[1];
            u64 b01 = bv.u[0], b23 = bv.u[1];
            u64 b12 = pk(bv.f.y, bv.f.z);
            u64 b30 = pk(bv.f.w, bv.f.x);
            fma2(c[0][0], ap0, b01); fma2(c[0][1], ap0, b12);
            fma2(c[0][2], ap0, b23); fma2(c[0][3], ap0, b30);
            fma2(c[1][0], ap1, b01); fma2(c[1][1], ap1, b12);
            fma2(c[1][2], ap1, b23); fma2(c[1][3], ap1, b30);
            fma2(c[2][0], ap2, b01); fma2(c[2][1], ap2, b12);
            fma2(c[2][2], ap2, b23); fma2(c[2][3], ap2, b30);
            fma2(c[3][0], ap3, b01); fma2(c[3][1], ap3, b12);
            fma2(c[3][2], ap3, b23); fma2(c[3][3], ap3, b30);
        }
        __syncthreads();
    }

    float o[8][4];
#pragma unroll
    for (int rp = 0; rp < 4; rp++) {
        upk(c[rp][0], o[2*rp][0], o[2*rp+1][1]);
        upk(c[rp][1], o[2*rp][1], o[2*rp+1][2]);
        upk(c[rp][2], o[2*rp][2], o[2*rp+1][3]);
        upk(c[rp][3], o[2*rp][3], o[2*rp+1][0]);
    }
#pragma unroll
    for (int rr = 0; rr < 8; rr++) {
        size_t rbase = (size_t)(rowBase + ty * 8 + rr) * 256;
#pragma unroll
        for (int j = 0; j < 4; j++) {
            int col = colBase + tx * 4 + j;       // original col = n*32+h
            int pc = (col & 31) * 8 + (col >> 5); // transposed [h][n]
            g_x[rbase + pc] = o[rr][j];
        }
    }
}

// ---------------------------------------------------------------------------
// Kernel 2a: seed scan.  grid (vb=5, b=4), 256 threads, 1 v per thread.
// ---------------------------------------------------------------------------
__global__ __launch_bounds__(256) void k_seed(const int* __restrict__ targets) {
    __shared__ int tg[L_];
    int b = blockIdx.y;
    int v = blockIdx.x * 256 + threadIdx.x;
    for (int i = threadIdx.x; i < L_; i += 256)
        tg[i] = targets[(size_t)b * L_ + i];
    __syncthreads();

    int* seed = g_seed + (size_t)b * 32 * V_;
    int nxt = L_;
#pragma unroll 1
    for (int ch = 31; ch >= 0; --ch) {
        seed[(size_t)ch * V_ + v] = nxt;
#pragma unroll
        for (int ii = 31; ii >= 0; --ii) {
            int i = ch * 32 + ii;
            if (tg[i] == v) nxt = i;
        }
    }
}

// ---------------------------------------------------------------------------
// Kernel 3 (FUSED): logits GEMM (M=32768, N=1280, K=32) + tte + mask.
// Tile 256m x 64v, 256 threads, 16m x 4v micro-tile (A is warp-broadcast,
// LDS pressure ~48B/cyc at 8 warps).  A 256-m tile = 32 l-rows of one batch
// = exactly one seed chunk -> each block also runs the 32-row next-occurrence
// scan for its 64 v and writes the tte + mask slices it owns.
// Special case (scatter semantics): token_index[b, l>=1, v=0] = 0.
// ---------------------------------------------------------------------------
__global__ __launch_bounds__(256, 2) void k_fused(const float* __restrict__ W2,
                                                  const float* __restrict__ age,
                                                  const float* __restrict__ targets_age,
                                                  const int* __restrict__ targets,
                                                  float* __restrict__ out) {
    __shared__ float As[32][264];   // [h][m_local]  (pad to de-conflict stores)
    __shared__ float Bs[32][68];    // [h][v_local]
    __shared__ float ta[L_];        // targets_age for this batch
    __shared__ float ag_s[32];
    __shared__ int   tg_s[32];
    __shared__ int   sd_s[64];

    int tid = threadIdx.x;
    int tx = tid & 15, ty = tid >> 4;
    int v0 = blockIdx.x * 64;       // 0..19
    int m0 = blockIdx.y * 256;      // 0..127
    int row0 = m0 >> 3;             // b*L + l0
    int b = row0 >> 10, l0 = row0 & 1023;
    int ch = l0 >> 5;

    // A tile: 32 g_x rows (= 256 m) x 256 floats, contiguous 32KB.
    // g_x[r][h*8+n] -> As[h][rl*8+n]
    const float4* xsrc = (const float4*)(g_x + (size_t)row0 * 256);
#pragma unroll
    for (int p = 0; p < 8; p++) {
        int idx = tid + p * 256;            // 2048 float4
        float4 v4 = xsrc[idx];
        int rl = idx >> 6;                  // 0..31
        int rem = idx & 63;
        int h = rem >> 1, n4 = (rem & 1) << 2;
        *(float4*)&As[h][rl * 8 + n4] = v4;
    }
    // B tile: W2[h][v0+vl], 32x64
#pragma unroll
    for (int p = 0; p < 2; p++) {
        int idx = tid + p * 256;            // 512 float4
        int h = idx >> 4, vq = (idx & 15) << 2;
        *(float4*)&Bs[h][vq] = *(const float4*)&W2[(size_t)h * V_ + v0 + vq];
    }
    // tte/mask inputs
    *(float4*)&ta[tid * 4] = ((const float4*)(targets_age + (size_t)b * L_))[tid];
    if (tid < 32) {
        ag_s[tid] = age[(size_t)b * L_ + l0 + tid];
        tg_s[tid] = targets[(size_t)b * L_ + l0 + tid];
    }
    if (tid < 64)
        sd_s[tid] = g_seed[((size_t)b * 32 + ch) * V_ + v0 + tid];
    __syncthreads();

    // ---- GEMM mainloop: 16m x 4v, diagonal-packed FFMA2 ----
    u64 acc[8][4];
#pragma unroll
    for (int i = 0; i < 8; i++)
#pragma unroll
        for (int j = 0; j < 4; j++) acc[i][j] = 0;

#pragma unroll 8
    for (int k = 0; k < 32; k++) {
        F4U2 a0, a1, a2, a3, bv;
        a0.f = *(const float4*)&As[k][ty * 16];
        a1.f = *(const float4*)&As[k][ty * 16 + 4];
        a2.f = *(const float4*)&As[k][ty * 16 + 8];
        a3.f = *(const float4*)&As[k][ty * 16 + 12];
        bv.f = *(const float4*)&Bs[k][tx * 4];
        u64 ap[8] = {a0.u[0], a0.u[1], a1.u[0], a1.u[1],
                     a2.u[0], a2.u[1], a3.u[0], a3.u[1]};
        u64 bp0 = bv.u[0], bp2 = bv.u[1];
        u64 bp1 = pk(bv.f.y, bv.f.z);
        u64 bp3 = pk(bv.f.w, bv.f.x);
#pragma unroll
        for (int i = 0; i < 8; i++) {
            fma2(acc[i][0], ap[i], bp0);
            fma2(acc[i][1], ap[i], bp1);
            fma2(acc[i][2], ap[i], bp2);
            fma2(acc[i][3], ap[i], bp3);
        }
    }

    // Decode diagonal pairs -> c[16][4]
    float c[16][4];
#pragma unroll
    for (int i = 0; i < 8; i++) {
        upk(acc[i][0], c[2*i][0], c[2*i+1][1]);
        upk(acc[i][1], c[2*i][1], c[2*i+1][2]);
        upk(acc[i][2], c[2*i][2], c[2*i+1][3]);
        upk(acc[i][3], c[2*i][3], c[2*i+1][0]);
    }

    // Store logits
#pragma unroll
    for (int mr = 0; mr < 16; mr++) {
        size_t off = (size_t)(m0 + ty * 16 + mr) * V_ + v0 + tx * 4;
        *(float4*)&out[off] = make_float4(c[mr][0], c[mr][1], c[mr][2], c[mr][3]);
    }

    // ---- tte + mask epilogue: thread = (v_local, row_group of 8) ----
    {
        int vl = tid & 63, rg = tid >> 6;     // rg uniform per warp
        int v = v0 + vl;
        int nxt = sd_s[vl];
        float* out_tte  = out + TTE_OFF  + (size_t)b * L_ * V_;
        float* out_mask = out + MASK_OFF + (size_t)b * L_ * NBIN * V_;
        int lo_row = rg * 8;
        for (int ii = 31; ii >= lo_row; --ii) {
            if (tg_s[ii] == v) nxt = l0 + ii;
            if (ii < lo_row + 8) {
                int l = l0 + ii;
                int idx = nxt;
                if (v == 0 && l >= 1) idx = 0;
                bool ne = (idx == L_);
                float tt = ta[ne ? (L_ - 1) : idx] - ag_s[ii];
                out_tte[(size_t)l * V_ + v] = tt;
                size_t mb = (size_t)l * NBIN * V_ + v;
#pragma unroll
                for (int n = 0; n < NBIN; n++) {
                    float lo = 1.25f * n;
                    float hi = lo + 1.25f;
                    out_mask[mb + (size_t)n * V_] = ((tt >= lo && tt < hi) || ne) ? 1.0f : 0.0f;
                }
            }
        }
    }
}

// ---------------------------------------------------------------------------
static cudaStream_t g_s2;
static cudaEvent_t g_e1, g_e2;
static struct StreamInit {
    StreamInit() {
        cudaStreamCreateWithFlags(&g_s2, cudaStreamNonBlocking);
        cudaEventCreateWithFlags(&g_e1, cudaEventDisableTiming);
        cudaEventCreateWithFlags(&g_e2, cudaEventDisableTiming);
    }
} g_stream_init;

extern "C" void kernel_launch(void* const* d_in, const int* in_sizes, int n_in,
                              void* d_out, int out_size) {
    const float* h       = (const float*)d_in[0];  // (B,L,768)
    const float* age     = (const float*)d_in[1];  // (B,L)
    const float* tage    = (const float*)d_in[2];  // (B,L)
    const int*   targets = (const int*)d_in[4];    // (B,L) int32
    const float* W1      = (const float*)d_in[5];  // (768,256)
    const float* W2      = (const float*)d_in[6];  // (32,1280)
    float* out = (float*)d_out;

    // Seeds (stream 2) overlap gemm1 (stream 0); fused kernel joins both.
    cudaEventRecord(g_e1, 0);
    cudaStreamWaitEvent(g_s2, g_e1, 0);
    k_seed<<<dim3(5, B_), 256, 0, g_s2>>>(targets);
    cudaEventRecord(g_e2, g_s2);

    k_gemm1<<<dim3(4, 32), 256>>>(h, W1);
    cudaStreamWaitEvent(0, g_e2, 0);
    k_fused<<<dim3(20, 128), 256>>>(W2, age, tage, targets, out);
}